// round 6
// baseline (speedup 1.0000x reference)
#include <cuda_runtime.h>
#include <cstdint>

#define D_DIM    256
#define M_TOT    8192
#define N_TOT    8192
#define TM       64
#define TN       256
#define NTHREADS 256
#define NTILES   (N_TOT / TN)          // 32
#define KCHUNKS  16                    // k-chunks per n-tile (each = 2 k8 steps)
#define TOTCH    (NTILES * KCHUNKS)    // 512

// smem byte offsets (dynamic)
#define SM_A      0                    // fp32 permuted A: 4mt x 32k8 x 128 fl = 64 KB
#define SM_B0     65536                // B buffer 0: 256 rows x 12 float4 = 48 KB
#define SM_B1     114688               // B buffer 1
#define SM_BYTES  163840
#define BROW      12                   // B row stride in float4 (8 data + 4 pad)

__device__ float  g_esq[N_TOT];
__device__ float4 g_bpack[N_TOT * 128];   // [n][k8 0..31][kq 0..3] {h,h4,l,l4}

// ---------------------------------------------------------------------------
__device__ __forceinline__ void split_tf32(float a, float& h, float& l) {
    uint32_t u = __float_as_uint(a);
    h = __uint_as_float((u + 0x1000u) & 0xFFFFE000u);
    l = a - h;                          // exact; HMMA truncates low bits safely
}
__device__ __forceinline__ void mma1688(float* d, const uint32_t* a,
                                        const uint32_t* b) {
    asm volatile(
        "mma.sync.aligned.m16n8k8.row.col.f32.tf32.tf32.f32 "
        "{%0,%1,%2,%3}, {%4,%5,%6,%7}, {%8,%9}, {%0,%1,%2,%3};"
        : "+f"(d[0]), "+f"(d[1]), "+f"(d[2]), "+f"(d[3])
        : "r"(a[0]), "r"(a[1]), "r"(a[2]), "r"(a[3]), "r"(b[0]), "r"(b[1]));
}
__device__ __forceinline__ uint32_t smem_u32(const void* p) {
    uint32_t a;
    asm("{ .reg .u64 t; cvta.to.shared.u64 t, %1; cvt.u32.u64 %0, t; }"
        : "=r"(a) : "l"(p));
    return a;
}
__device__ __forceinline__ void cp16(uint32_t dst, const void* src) {
    asm volatile("cp.async.cg.shared.global [%0], [%1], 16;"
                 :: "r"(dst), "l"(src) : "memory");
}
#define CP_COMMIT() asm volatile("cp.async.commit_group;" ::: "memory")
#define CP_WAIT1()  asm volatile("cp.async.wait_group 1;" ::: "memory")
#define CP_WAIT0()  asm volatile("cp.async.wait_group 0;" ::: "memory")

// ---------------------------------------------------------------------------
__global__ void esq_kernel(const float* __restrict__ embed) {
    int w = (blockIdx.x * blockDim.x + threadIdx.x) >> 5;
    int lane = threadIdx.x & 31;
    if (w >= N_TOT) return;
    const float4* row = (const float4*)(embed + (size_t)w * D_DIM);
    float s = 0.f;
    #pragma unroll
    for (int i = lane; i < D_DIM / 4; i += 32) {
        float4 v = row[i];
        s += v.x * v.x + v.y * v.y + v.z * v.z + v.w * v.w;
    }
    #pragma unroll
    for (int o = 16; o; o >>= 1) s += __shfl_xor_sync(0xFFFFFFFFu, s, o);
    if (lane == 0) g_esq[w] = s;
}

// prep: pack embed into B-fragment layout {h(k), h(k+4), l(k), l(k+4)}
__global__ void bpack_kernel(const float* __restrict__ embed) {
    int i = blockIdx.x * blockDim.x + threadIdx.x;     // 0 .. 8192*128-1
    if (i >= N_TOT * 128) return;
    int n  = i >> 7;
    int f  = i & 127;
    int k8 = f >> 2, kq = f & 3;
    int k  = k8 * 8 + kq;
    float v0 = embed[(size_t)n * D_DIM + k];
    float v1 = embed[(size_t)n * D_DIM + k + 4];
    float h0, l0, h1, l1;
    split_tf32(v0, h0, l0);
    split_tf32(v1, h1, l1);
    g_bpack[i] = make_float4(h0, h1, l0, l1);
}

// ---------------------------------------------------------------------------
// Fused 3xTF32 GEMM + argmin + gather.
// CTA 256 thr / 8 warps; TM=64 rows resident (fp32, frag-permuted);
// TN=256 cols streamed; warp tile 64x32 (mt=4, ntl=4);
// B via cp.async double buffer from prepacked gmem fragments.
// ---------------------------------------------------------------------------
extern __shared__ char dsm[];

__global__ __launch_bounds__(NTHREADS, 1) void vq_mma_kernel(
    const float* __restrict__ x,
    const float* __restrict__ embed,
    float* __restrict__ out)
{
    __shared__ unsigned long long red[TM];
    __shared__ int bestrow[TM];

    float* smA = (float*)dsm;
    const int tid  = threadIdx.x;
    const int lane = tid & 31;
    const int wid  = tid >> 5;
    const int mBase = blockIdx.x * TM;

    const uint32_t smBase = smem_u32(dsm);
    const uint32_t bAddr[2] = { smBase + SM_B0 + (uint32_t)tid * (BROW * 16),
                                smBase + SM_B1 + (uint32_t)tid * (BROW * 16) };

    if (tid < TM) red[tid] = 0xFFFFFFFFFFFFFFFFull;

    // ---- issue B chunks 0,1 first (overlap with A staging)
    #pragma unroll
    for (int c0 = 0; c0 < 2; c0++) {
        const float4* src = g_bpack + (size_t)tid * 128 + c0 * 8;  // nt=0
        #pragma unroll
        for (int q = 0; q < 8; q++) cp16(bAddr[c0] + q * 16, src + q);
        CP_COMMIT();
    }

    // ---- A: load 64 rows x 256 k fp32, store fragment-permuted
    #pragma unroll 4
    for (int s = 0; s < 16; s++) {
        int fidx = tid + s * NTHREADS;
        int row = fidx >> 6, q = fidx & 63;
        float4 v = ((const float4*)(x + (size_t)(mBase + row) * D_DIM))[q];
        int mt = row >> 4, ml = row & 15;
        float vv[4] = {v.x, v.y, v.z, v.w};
        #pragma unroll
        for (int e = 0; e < 4; e++) {
            int kk = q * 4 + e;
            int k8 = kk >> 3, c = kk & 7;
            int t    = ((ml & 7) << 2) | (c & 3);
            int slot = ((ml >> 3) & 1) | (((c >> 2) & 1) << 1);
            smA[(mt * 32 + k8) * 128 + t * 4 + slot] = vv[e];
        }
    }

    float bestv[8];
    int   besti[8];
    #pragma unroll
    for (int i = 0; i < 8; i++) { bestv[i] = 3.4e38f; besti[i] = 0; }

    float acc[4][4][4];

    for (int c = 0; c < TOTCH; c++) {
        const int kc = c & (KCHUNKS - 1);
        const int ntB = (c >> 4) * TN;

        if (c + 1 < TOTCH) CP_WAIT1(); else CP_WAIT0();
        __syncthreads();                       // B chunk c visible to all

        if (kc == 0) {
            #pragma unroll
            for (int i = 0; i < 4; i++)
                #pragma unroll
                for (int j = 0; j < 4; j++)
                    #pragma unroll
                    for (int e = 0; e < 4; e++) acc[i][j][e] = 0.f;
        }

        const float4* bb = (const float4*)(dsm + (((c & 1) ? SM_B1 : SM_B0)));

        #pragma unroll
        for (int j = 0; j < 2; j++) {          // 2 k8 steps per chunk
            const int k8g = kc * 2 + j;
            // A fragments: fp32 LDS.128 then register hi/lo split
            uint32_t aH[4][4], aL[4][4];
            #pragma unroll
            for (int mt = 0; mt < 4; mt++) {
                float4 af = *(const float4*)&smA[(mt * 32 + k8g) * 128 + lane * 4];
                float vv[4] = {af.x, af.y, af.z, af.w};
                #pragma unroll
                for (int e = 0; e < 4; e++) {
                    float h, l;
                    split_tf32(vv[e], h, l);
                    aH[mt][e] = __float_as_uint(h);
                    aL[mt][e] = __float_as_uint(l);
                }
            }
            #pragma unroll
            for (int ntl = 0; ntl < 4; ntl++) {
                int nloc = wid * 32 + ntl * 8 + (lane >> 2);
                float4 bp = bb[nloc * BROW + j * 4 + (lane & 3)];
                uint32_t bH[2] = {__float_as_uint(bp.x), __float_as_uint(bp.y)};
                uint32_t bL[2] = {__float_as_uint(bp.z), __float_as_uint(bp.w)};
                #pragma unroll
                for (int mt = 0; mt < 4; mt++) {
                    mma1688(acc[mt][ntl], aH[mt], bH);   // hi*hi
                    mma1688(acc[mt][ntl], aH[mt], bL);   // hi*lo
                    mma1688(acc[mt][ntl], aL[mt], bH);   // lo*hi
                }
            }
        }

        __syncthreads();                        // everyone done reading buffer
        if (c + 2 < TOTCH) {                    // refill this buffer w/ chunk c+2
            int nc = c + 2;
            const float4* src = g_bpack
                + (size_t)((nc >> 4) * TN + tid) * 128 + (nc & 15) * 8;
            uint32_t d = bAddr[c & 1];
            #pragma unroll
            for (int q = 0; q < 8; q++) cp16(d + q * 16, src + q);
            CP_COMMIT();
        }

        // ---- epilogue once per n-tile
        if (kc == KCHUNKS - 1) {
            #pragma unroll
            for (int ntl = 0; ntl < 4; ntl++) {
                int c0 = ntB + wid * 32 + ntl * 8 + 2 * (lane & 3);
                float e0 = __ldg(&g_esq[c0]);
                float e1 = __ldg(&g_esq[c0 + 1]);
                #pragma unroll
                for (int mt = 0; mt < 4; mt++) {
                    float s0 = e0 - 2.0f * acc[mt][ntl][0];
                    float s1 = e1 - 2.0f * acc[mt][ntl][1];
                    float s2 = e0 - 2.0f * acc[mt][ntl][2];
                    float s3 = e1 - 2.0f * acc[mt][ntl][3];
                    int bl = mt * 2, bh = mt * 2 + 1;
                    if (s0 < bestv[bl]) { bestv[bl] = s0; besti[bl] = c0; }
                    if (s1 < bestv[bl]) { bestv[bl] = s1; besti[bl] = c0 + 1; }
                    if (s2 < bestv[bh]) { bestv[bh] = s2; besti[bh] = c0; }
                    if (s3 < bestv[bh]) { bestv[bh] = s3; besti[bh] = c0 + 1; }
                }
            }
        }
    }

    // ---- CTA reduce: packed (orderable score | idx) smem atomicMin
    __syncthreads();
    #pragma unroll
    for (int i = 0; i < 8; i++) {
        int mt = i >> 1, h = i & 1;
        int r = mt * 16 + (lane >> 2) + h * 8;
        uint32_t u = __float_as_uint(bestv[i]);
        u = (u & 0x80000000u) ? ~u : (u | 0x80000000u);
        unsigned long long key =
            ((unsigned long long)u << 32) | (uint32_t)besti[i];
        atomicMin(&red[r], key);
    }
    __syncthreads();

    if (tid < TM) {
        int idx = (int)(red[tid] & 0xFFFFFFFFull);
        bestrow[tid] = idx;
        out[(long long)M_TOT * D_DIM + mBase + tid] = (float)idx;
    }
    __syncthreads();

    // ---- gather (exact fp32 rows)
    for (int i = tid; i < TM * (D_DIM / 4); i += NTHREADS) {
        int r = i >> 6, kv = i & 63;
        float4 v = ((const float4*)(embed + (size_t)bestrow[r] * D_DIM))[kv];
        ((float4*)(out + (size_t)(mBase + r) * D_DIM))[kv] = v;
    }
}

// ---------------------------------------------------------------------------
extern "C" void kernel_launch(void* const* d_in, const int* in_sizes, int n_in,
                              void* d_out, int out_size)
{
    const float* x     = (const float*)d_in[0];
    const float* embed = (const float*)d_in[1];
    float*       out   = (float*)d_out;

    esq_kernel<<<(N_TOT * 32 + 255) / 256, 256>>>(embed);
    bpack_kernel<<<(N_TOT * 128 + 255) / 256, 256>>>(embed);

    cudaFuncSetAttribute(vq_mma_kernel,
                         cudaFuncAttributeMaxDynamicSharedMemorySize, SM_BYTES);
    vq_mma_kernel<<<M_TOT / TM, NTHREADS, SM_BYTES>>>(x, embed, out);
}

// round 7
// speedup vs baseline: 1.3530x; 1.3530x over previous
#include <cuda_runtime.h>
#include <cstdint>

#define D_DIM    256
#define M_TOT    8192
#define N_TOT    8192
#define TM       64
#define TN       64
#define NTHREADS 256
#define TOTCH    ((N_TOT / TN) * 2)    // 256 chunks (K split in 2 per tile)

// smem layout (dynamic, floats/bytes)
#define SM_A_FLOATS   (TM * D_DIM)           // 16384 floats = 64 KB
#define BROW4         68                      // B row stride in float4 (64 + 4 pad)
#define SM_BUF_FLOAT4 (TN * BROW4)            // 4352 float4 = 69632 B
#define SM_BYTES      (SM_A_FLOATS * 4 + 2 * SM_BUF_FLOAT4 * 16)   // 204800

__device__ float  g_esq[N_TOT];
__device__ float4 g_bpack[N_TOT * 128];   // [n][k8 0..31][kq 0..3] {h,h4,l,l4}

// ---------------------------------------------------------------------------
__device__ __forceinline__ void split_tf32(float a, float& h, float& l) {
    uint32_t u = __float_as_uint(a);
    h = __uint_as_float((u + 0x1000u) & 0xFFFFE000u);
    l = a - h;                          // exact residual; fits tf32 mantissa
}
__device__ __forceinline__ void mma1688(float* d, const uint32_t* a,
                                        const uint32_t* b) {
    asm volatile(
        "mma.sync.aligned.m16n8k8.row.col.f32.tf32.tf32.f32 "
        "{%0,%1,%2,%3}, {%4,%5,%6,%7}, {%8,%9}, {%0,%1,%2,%3};"
        : "+f"(d[0]), "+f"(d[1]), "+f"(d[2]), "+f"(d[3])
        : "r"(a[0]), "r"(a[1]), "r"(a[2]), "r"(a[3]), "r"(b[0]), "r"(b[1]));
}

// ---------------------------------------------------------------------------
__global__ void esq_kernel(const float* __restrict__ embed) {
    int w = (blockIdx.x * blockDim.x + threadIdx.x) >> 5;
    int lane = threadIdx.x & 31;
    if (w >= N_TOT) return;
    const float4* row = (const float4*)(embed + (size_t)w * D_DIM);
    float s = 0.f;
    #pragma unroll
    for (int i = lane; i < D_DIM / 4; i += 32) {
        float4 v = row[i];
        s += v.x * v.x + v.y * v.y + v.z * v.z + v.w * v.w;
    }
    #pragma unroll
    for (int o = 16; o; o >>= 1) s += __shfl_xor_sync(0xFFFFFFFFu, s, o);
    if (lane == 0) g_esq[w] = s;
}

// prep: pack embed into B-fragment layout {h(k), h(k+4), l(k), l(k+4)}
__global__ void bpack_kernel(const float* __restrict__ embed) {
    int i = blockIdx.x * blockDim.x + threadIdx.x;     // 0 .. 8192*128-1
    if (i >= N_TOT * 128) return;
    int n  = i >> 7;
    int f  = i & 127;
    int k8 = f >> 2, kq = f & 3;
    int k  = k8 * 8 + kq;
    float v0 = embed[(size_t)n * D_DIM + k];
    float v1 = embed[(size_t)n * D_DIM + k + 4];
    float h0, l0, h1, l1;
    split_tf32(v0, h0, l0);
    split_tf32(v1, h1, l1);
    g_bpack[i] = make_float4(h0, h1, l0, l1);
}

// ---------------------------------------------------------------------------
// Fused 3xTF32 mma.sync GEMM + argmin + gather.  (R5 skeleton)
// CTA 256 thr / 8 warps (2m x 4n), warp tile 32x16; TM=64 resident fp32 A;
// TN=64 streamed, K in 2 chunks of 128; B double-buffered packed fragments.
// ---------------------------------------------------------------------------
extern __shared__ float dsm[];

__global__ __launch_bounds__(NTHREADS, 1) void vq_mma_kernel(
    const float* __restrict__ x,
    const float* __restrict__ embed,
    float* __restrict__ out)
{
    __shared__ unsigned long long red[TM];
    __shared__ int bestrow[TM];

    float*  smA  = dsm;
    float4* buf0 = (float4*)(dsm + SM_A_FLOATS);
    float4* buf1 = buf0 + SM_BUF_FLOAT4;

    const int tid  = threadIdx.x;
    const int lane = tid & 31;
    const int wid  = tid >> 5;
    const int wm   = wid & 1;          // m half
    const int wn   = wid >> 1;         // n quarter
    const int mBase = blockIdx.x * TM;

    if (tid < TM) red[tid] = 0xFFFFFFFFFFFFFFFFull;

    // ---- A: 64 rows x 256 k fp32, fragment-permuted (single copy)
    #pragma unroll 4
    for (int s = 0; s < 16; s++) {
        int fidx = tid + s * NTHREADS;
        int row = fidx >> 6, q = fidx & 63;
        float4 v = ((const float4*)(x + (size_t)(mBase + row) * D_DIM))[q];
        int mt = row >> 4, ml = row & 15;
        float vv[4] = {v.x, v.y, v.z, v.w};
        #pragma unroll
        for (int e = 0; e < 4; e++) {
            int kk = q * 4 + e;
            int k8 = kk >> 3, c = kk & 7;
            int t    = ((ml & 7) << 2) | (c & 3);
            int slot = ((ml >> 3) & 1) | (((c >> 2) & 1) << 1);
            smA[(mt * 32 + k8) * 128 + t * 4 + slot] = vv[e];
        }
    }

    // ---- B chunk 0 -> buf0 directly; chunk 1 -> pf
    // warp handles rows wid, wid+8, ..., wid+56; lane -> float4 l and 32+l
    float4 pf[16];
    {
        const float4* src = g_bpack + (size_t)wid * 128;     // chunk 0: nt0,kc0
        #pragma unroll
        for (int s = 0; s < 8; s++) {
            buf0[(wid + 8 * s) * BROW4 + lane]      = src[(size_t)s * 8 * 128 + lane];
            buf0[(wid + 8 * s) * BROW4 + 32 + lane] = src[(size_t)s * 8 * 128 + 32 + lane];
        }
        const float4* src1 = g_bpack + (size_t)wid * 128 + 64;  // chunk 1: nt0,kc1
        #pragma unroll
        for (int s = 0; s < 8; s++) {
            pf[2 * s]     = src1[(size_t)s * 8 * 128 + lane];
            pf[2 * s + 1] = src1[(size_t)s * 8 * 128 + 32 + lane];
        }
    }

    float bestv[4];
    int   besti[4];
    #pragma unroll
    for (int i = 0; i < 4; i++) { bestv[i] = 3.4e38f; besti[i] = 0; }

    float acc[2][2][4];

    for (int c = 0; c < TOTCH; c++) {
        float4* cur = (c & 1) ? buf1 : buf0;
        float4* nxt = (c & 1) ? buf0 : buf1;

        // chunk c stored (iter c-1 / prologue); compute c-1 done -> nxt free
        __syncthreads();

        // store pf (chunk c+1) into nxt
        if (c + 1 < TOTCH) {
            #pragma unroll
            for (int s = 0; s < 8; s++) {
                nxt[(wid + 8 * s) * BROW4 + lane]      = pf[2 * s];
                nxt[(wid + 8 * s) * BROW4 + 32 + lane] = pf[2 * s + 1];
            }
        }
        // prefetch chunk c+2
        if (c + 2 < TOTCH) {
            int nc = c + 2;
            const float4* src = g_bpack
                + (size_t)((nc >> 1) * TN + wid) * 128 + (nc & 1) * 64;
            #pragma unroll
            for (int s = 0; s < 8; s++) {
                pf[2 * s]     = src[(size_t)s * 8 * 128 + lane];
                pf[2 * s + 1] = src[(size_t)s * 8 * 128 + 32 + lane];
            }
        }

        if ((c & 1) == 0) {
            #pragma unroll
            for (int i = 0; i < 2; i++)
                #pragma unroll
                for (int j = 0; j < 2; j++)
                    #pragma unroll
                    for (int e = 0; e < 4; e++) acc[i][j][e] = 0.f;
        }

        // ---- compute 16 k8 steps of chunk c
        #pragma unroll 4
        for (int jj = 0; jj < 16; jj++) {
            const int k8g = (c & 1) * 16 + jj;
            uint32_t aH[2][4], aL[2][4];
            #pragma unroll
            for (int mt = 0; mt < 2; mt++) {
                int mtg = wm * 2 + mt;
                float4 af = *(const float4*)&smA[(mtg * 32 + k8g) * 128 + lane * 4];
                float vv[4] = {af.x, af.y, af.z, af.w};
                #pragma unroll
                for (int e = 0; e < 4; e++) {
                    float h, l;
                    split_tf32(vv[e], h, l);
                    aH[mt][e] = __float_as_uint(h);
                    aL[mt][e] = __float_as_uint(l);
                }
            }
            uint32_t bH[2][2], bL[2][2];
            #pragma unroll
            for (int ntl = 0; ntl < 2; ntl++) {
                int nloc = wn * 16 + ntl * 8 + (lane >> 2);
                float4 bp = cur[nloc * BROW4 + jj * 4 + (lane & 3)];
                bH[ntl][0] = __float_as_uint(bp.x);
                bH[ntl][1] = __float_as_uint(bp.y);
                bL[ntl][0] = __float_as_uint(bp.z);
                bL[ntl][1] = __float_as_uint(bp.w);
            }
            #pragma unroll
            for (int mt = 0; mt < 2; mt++)
                #pragma unroll
                for (int ntl = 0; ntl < 2; ntl++) {
                    mma1688(acc[mt][ntl], aH[mt], bH[ntl]);   // hi*hi
                    mma1688(acc[mt][ntl], aH[mt], bL[ntl]);   // hi*lo
                    mma1688(acc[mt][ntl], aL[mt], bH[ntl]);   // lo*hi
                }
        }

        // ---- epilogue at end of each n-tile (odd chunk)
        if (c & 1) {
            int ntB = (c >> 1) * TN;
            #pragma unroll
            for (int ntl = 0; ntl < 2; ntl++) {
                int c0 = ntB + wn * 16 + ntl * 8 + 2 * (lane & 3);
                float e0 = __ldg(&g_esq[c0]);
                float e1 = __ldg(&g_esq[c0 + 1]);
                #pragma unroll
                for (int mt = 0; mt < 2; mt++) {
                    float s0 = e0 - 2.0f * acc[mt][ntl][0];
                    float s1 = e1 - 2.0f * acc[mt][ntl][1];
                    float s2 = e0 - 2.0f * acc[mt][ntl][2];
                    float s3 = e1 - 2.0f * acc[mt][ntl][3];
                    int bl = mt * 2, bh = mt * 2 + 1;
                    if (s0 < bestv[bl]) { bestv[bl] = s0; besti[bl] = c0; }
                    if (s1 < bestv[bl]) { bestv[bl] = s1; besti[bl] = c0 + 1; }
                    if (s2 < bestv[bh]) { bestv[bh] = s2; besti[bh] = c0; }
                    if (s3 < bestv[bh]) { bestv[bh] = s3; besti[bh] = c0 + 1; }
                }
            }
        }
    }

    // ---- CTA reduce: packed (orderable score | idx) smem atomicMin
    __syncthreads();
    #pragma unroll
    for (int i = 0; i < 4; i++) {
        int mt = i >> 1, h = i & 1;
        int r = wm * 32 + mt * 16 + (lane >> 2) + h * 8;
        uint32_t u = __float_as_uint(bestv[i]);
        u = (u & 0x80000000u) ? ~u : (u | 0x80000000u);
        unsigned long long key =
            ((unsigned long long)u << 32) | (uint32_t)besti[i];
        atomicMin(&red[r], key);
    }
    __syncthreads();

    if (tid < TM) {
        int idx = (int)(red[tid] & 0xFFFFFFFFull);
        bestrow[tid] = idx;
        out[(long long)M_TOT * D_DIM + mBase + tid] = (float)idx;
    }
    __syncthreads();

    // ---- gather (exact fp32 rows)
    for (int i = tid; i < TM * (D_DIM / 4); i += NTHREADS) {
        int r = i >> 6, kv = i & 63;
        float4 v = ((const float4*)(embed + (size_t)bestrow[r] * D_DIM))[kv];
        ((float4*)(out + (size_t)(mBase + r) * D_DIM))[kv] = v;
    }
}

// ---------------------------------------------------------------------------
extern "C" void kernel_launch(void* const* d_in, const int* in_sizes, int n_in,
                              void* d_out, int out_size)
{
    const float* x     = (const float*)d_in[0];
    const float* embed = (const float*)d_in[1];
    float*       out   = (float*)d_out;

    esq_kernel<<<(N_TOT * 32 + 255) / 256, 256>>>(embed);
    bpack_kernel<<<(N_TOT * 128 + 255) / 256, 256>>>(embed);

    cudaFuncSetAttribute(vq_mma_kernel,
                         cudaFuncAttributeMaxDynamicSharedMemorySize, SM_BYTES);
    vq_mma_kernel<<<M_TOT / TM, NTHREADS, SM_BYTES>>>(x, embed, out);
}

// round 8
// speedup vs baseline: 1.4764x; 1.0912x over previous
#include <cuda_runtime.h>
#include <cstdint>
#include <math.h>

#define D_DIM    256
#define M_TOT    8192
#define N_TOT    8192
#define TM       64
#define TN       256
#define NTHREADS 256
#define KCH      32
#define TOTCH    ((N_TOT / TN) * (D_DIM / KCH))   // 256
#define CAND_MAX 256

#define SM_A_FLOATS (TM * D_DIM)          // 16384 floats = 64 KB
#define BUF_FLOATS  (TN * 40)             // row stride 40 floats -> 40960 B
#define SM_BYTES    (SM_A_FLOATS * 4 + 3 * BUF_FLOATS * 4)   // 188416

__device__ float    g_bpk[N_TOT * D_DIM];   // tf32-rounded, pair-permuted B
__device__ float    g_esq[N_TOT];
__device__ int      g_cand[M_TOT * CAND_MAX];
__device__ int      g_cnt[M_TOT];
__device__ unsigned g_mx2, g_me2;           // max squared norms (uint-encoded)

// ---------------------------------------------------------------------------
__device__ __forceinline__ float tf32_rn(float a) {
    uint32_t u;
    asm("cvt.rna.tf32.f32 %0, %1;" : "=r"(u) : "f"(a));
    return __uint_as_float(u);
}
__device__ __forceinline__ void mma1688(float* d, const uint32_t* a,
                                        const uint32_t* b) {
    asm volatile(
        "mma.sync.aligned.m16n8k8.row.col.f32.tf32.tf32.f32 "
        "{%0,%1,%2,%3}, {%4,%5,%6,%7}, {%8,%9}, {%0,%1,%2,%3};"
        : "+f"(d[0]), "+f"(d[1]), "+f"(d[2]), "+f"(d[3])
        : "r"(a[0]), "r"(a[1]), "r"(a[2]), "r"(a[3]), "r"(b[0]), "r"(b[1]));
}
__device__ __forceinline__ uint32_t smem_u32(const void* p) {
    uint32_t a;
    asm("{ .reg .u64 t; cvta.to.shared.u64 t, %1; cvt.u32.u64 %0, t; }"
        : "=r"(a) : "l"(p));
    return a;
}
__device__ __forceinline__ void cp16(uint32_t dst, const void* src) {
    asm volatile("cp.async.cg.shared.global [%0], [%1], 16;"
                 :: "r"(dst), "l"(src) : "memory");
}
#define CP_COMMIT() asm volatile("cp.async.commit_group;" ::: "memory")
#define CP_WAIT1()  asm volatile("cp.async.wait_group 1;" ::: "memory")
#define CP_WAIT0()  asm volatile("cp.async.wait_group 0;" ::: "memory")

__device__ __forceinline__ unsigned enc(float f) {
    unsigned u = __float_as_uint(f);
    return (u & 0x80000000u) ? ~u : (u | 0x80000000u);
}
__device__ __forceinline__ float dec(unsigned u) {
    return (u & 0x80000000u) ? __uint_as_float(u & 0x7FFFFFFFu)
                             : __uint_as_float(~u);
}

// ---------------------------------------------------------------------------
__global__ void init_kernel() {
    int i = blockIdx.x * blockDim.x + threadIdx.x;
    if (i < M_TOT) g_cnt[i] = 0;
    if (i == 0) { g_mx2 = 0u; g_me2 = 0u; }
}

// norms: warp per row; rows 0..8191 = x, 8192..16383 = embed (also g_esq)
__global__ void norm_kernel(const float* __restrict__ x,
                            const float* __restrict__ embed) {
    int rid = (blockIdx.x * blockDim.x + threadIdx.x) >> 5;
    int lane = threadIdx.x & 31;
    if (rid >= 2 * M_TOT) return;
    const float* row = (rid < M_TOT) ? (x + (size_t)rid * D_DIM)
                                     : (embed + (size_t)(rid - M_TOT) * D_DIM);
    float s = 0.f;
    const float4* r4 = (const float4*)row;
    #pragma unroll
    for (int i = lane; i < D_DIM / 4; i += 32) {
        float4 v = r4[i];
        s += v.x * v.x + v.y * v.y + v.z * v.z + v.w * v.w;
    }
    #pragma unroll
    for (int o = 16; o; o >>= 1) s += __shfl_xor_sync(0xFFFFFFFFu, s, o);
    if (lane == 0) {
        if (rid < M_TOT) atomicMax(&g_mx2, __float_as_uint(s));
        else { g_esq[rid - M_TOT] = s; atomicMax(&g_me2, __float_as_uint(s)); }
    }
}

// pack B: tf32-rounded, pair-permuted: row pos p -> orig k
// p = kc*32 + j*8 + kq*2 + h  maps  k = kc*32 + j*8 + kq + h*4
__global__ void bpk_kernel(const float* __restrict__ embed) {
    int i = blockIdx.x * blockDim.x + threadIdx.x;
    if (i >= N_TOT * D_DIM) return;
    int n = i >> 8, p = i & 255;
    int kc = p >> 5, r = p & 31;
    int j = r >> 3, kq = (r >> 1) & 3, h = r & 1;
    int k = kc * 32 + j * 8 + kq + h * 4;
    g_bpk[i] = tf32_rn(embed[(size_t)n * D_DIM + k]);
}

// ---------------------------------------------------------------------------
// Pass 1: 1xTF32 GEMM + running-min + candidate append.
// 256 thr / 8 warps (2m x 4n); warp tile 32 x 64; TN=256 streamed;
// K-chunks of 32, cp.async triple buffer, single barrier per chunk.
// ---------------------------------------------------------------------------
extern __shared__ float dsm[];

__device__ __forceinline__ void append_cand(int grow, int col) {
    int idx = atomicAdd(&g_cnt[grow], 1);
    if (idx < CAND_MAX) g_cand[grow * CAND_MAX + idx] = col;
}

__global__ __launch_bounds__(NTHREADS, 1) void vq1_kernel(
    const float* __restrict__ x)
{
    __shared__ unsigned red[TM];
    float* smA = dsm;
    const uint32_t smBase = smem_u32(dsm);

    const int tid  = threadIdx.x;
    const int lane = tid & 31;
    const int wid  = tid >> 5;
    const int wm   = wid & 1;
    const int wn   = wid >> 1;
    const int mBase = blockIdx.x * TM;

    if (tid < TM) red[tid] = 0xFFFFFFFFu;

    const float th = 4.2e-3f * sqrtf(__uint_as_float(g_mx2) *
                                     __uint_as_float(g_me2)) + 0.02f;

    // prologue: issue B chunks 0,1 (n-tile 0, kc 0,1)
    #pragma unroll
    for (int c0 = 0; c0 < 2; c0++) {
        uint32_t dstB = smBase + SM_A_FLOATS * 4 + (uint32_t)c0 * (BUF_FLOATS * 4);
        const float* src = g_bpk + c0 * KCH;    // + row*256 + seg*4
        #pragma unroll
        for (int i = 0; i < 8; i++) {
            int g = tid + i * 256, row = g >> 3, seg = g & 7;
            cp16(dstB + row * 160 + seg * 16, src + row * 256 + seg * 4);
        }
        CP_COMMIT();
    }

    // A: 64 rows x 256 k, tf32-rounded, mma-fragment-permuted
    #pragma unroll 4
    for (int s = 0; s < 16; s++) {
        int fidx = tid + s * NTHREADS;
        int row = fidx >> 6, q = fidx & 63;
        float4 v = ((const float4*)(x + (size_t)(mBase + row) * D_DIM))[q];
        int mt = row >> 4, ml = row & 15;
        float vv[4] = {v.x, v.y, v.z, v.w};
        #pragma unroll
        for (int e = 0; e < 4; e++) {
            int kk = q * 4 + e;
            int k8 = kk >> 3, c = kk & 7;
            int t    = ((ml & 7) << 2) | (c & 3);
            int slot = ((ml >> 3) & 1) | (((c >> 2) & 1) << 1);
            smA[(mt * 32 + k8) * 128 + t * 4 + slot] = tf32_rn(vv[e]);
        }
    }

    float acc[2][8][4];

    for (int c = 0; c < TOTCH; c++) {
        if (c + 1 < TOTCH) CP_WAIT1(); else CP_WAIT0();
        __syncthreads();

        const int kc  = c & 7;
        const int ntB = (c >> 3) * TN;

        if (kc == 0) {
            #pragma unroll
            for (int i = 0; i < 2; i++)
                #pragma unroll
                for (int j = 0; j < 8; j++)
                    #pragma unroll
                    for (int e = 0; e < 4; e++) acc[i][j][e] = 0.f;
        }

        const float* bb = dsm + SM_A_FLOATS + (c % 3) * BUF_FLOATS;

        #pragma unroll
        for (int j = 0; j < 4; j++) {                 // 4 k8 steps
            const int k8g = kc * 4 + j;
            uint32_t aF[2][4];
            #pragma unroll
            for (int mt = 0; mt < 2; mt++) {
                int mtg = wm * 2 + mt;
                float4 af = *(const float4*)&smA[(mtg * 32 + k8g) * 128 + lane * 4];
                aF[mt][0] = __float_as_uint(af.x);
                aF[mt][1] = __float_as_uint(af.y);
                aF[mt][2] = __float_as_uint(af.z);
                aF[mt][3] = __float_as_uint(af.w);
            }
            #pragma unroll
            for (int ntl = 0; ntl < 8; ntl++) {
                int nloc = wn * 64 + ntl * 8 + (lane >> 2);
                float2 bp = *(const float2*)&bb[nloc * 40 + (j * 4 + (lane & 3)) * 2];
                uint32_t bF[2] = {__float_as_uint(bp.x), __float_as_uint(bp.y)};
                mma1688(acc[0][ntl], aF[0], bF);
                mma1688(acc[1][ntl], aF[1], bF);
            }
        }

        // refill freed buffer with chunk c+2
        if (c + 2 < TOTCH) {
            int nc = c + 2;
            uint32_t dstB = smBase + SM_A_FLOATS * 4
                          + (uint32_t)(nc % 3) * (BUF_FLOATS * 4);
            const float* src = g_bpk + (size_t)((nc >> 3) * TN) * 256
                             + (nc & 7) * KCH;
            #pragma unroll
            for (int i = 0; i < 8; i++) {
                int g = tid + i * 256, row = g >> 3, seg = g & 7;
                cp16(dstB + row * 160 + seg * 16, src + row * 256 + seg * 4);
            }
            CP_COMMIT();
        }

        // epilogue per n-tile: phase A (tighten red), phase B (append)
        if (kc == 7) {
            float rmin[4] = {3.4e38f, 3.4e38f, 3.4e38f, 3.4e38f};
            #pragma unroll
            for (int mt = 0; mt < 2; mt++)
                #pragma unroll
                for (int ntl = 0; ntl < 8; ntl++) {
                    int c0 = ntB + wn * 64 + ntl * 8 + 2 * (lane & 3);
                    float e0 = __ldg(&g_esq[c0]);
                    float e1 = __ldg(&g_esq[c0 + 1]);
                    float s0 = e0 - 2.0f * acc[mt][ntl][0];
                    float s1 = e1 - 2.0f * acc[mt][ntl][1];
                    float s2 = e0 - 2.0f * acc[mt][ntl][2];
                    float s3 = e1 - 2.0f * acc[mt][ntl][3];
                    rmin[mt*2]   = fminf(rmin[mt*2],   fminf(s0, s1));
                    rmin[mt*2+1] = fminf(rmin[mt*2+1], fminf(s2, s3));
                }
            #pragma unroll
            for (int q = 0; q < 4; q++) {
                int r = (wm * 2 + (q >> 1)) * 16 + (lane >> 2) + (q & 1) * 8;
                atomicMin(&red[r], enc(rmin[q]));
            }
            __syncthreads();
            #pragma unroll
            for (int mt = 0; mt < 2; mt++) {
                int r0 = (wm * 2 + mt) * 16 + (lane >> 2);
                float t0 = dec(red[r0]) + th;
                float t1 = dec(red[r0 + 8]) + th;
                #pragma unroll
                for (int ntl = 0; ntl < 8; ntl++) {
                    int c0 = ntB + wn * 64 + ntl * 8 + 2 * (lane & 3);
                    float e0 = __ldg(&g_esq[c0]);
                    float e1 = __ldg(&g_esq[c0 + 1]);
                    float s0 = e0 - 2.0f * acc[mt][ntl][0];
                    float s1 = e1 - 2.0f * acc[mt][ntl][1];
                    float s2 = e0 - 2.0f * acc[mt][ntl][2];
                    float s3 = e1 - 2.0f * acc[mt][ntl][3];
                    if (s0 <= t0) append_cand(mBase + r0, c0);
                    if (s1 <= t0) append_cand(mBase + r0, c0 + 1);
                    if (s2 <= t1) append_cand(mBase + r0 + 8, c0);
                    if (s3 <= t1) append_cand(mBase + r0 + 8, c0 + 1);
                }
            }
        }
    }
}

// ---------------------------------------------------------------------------
// Pass 2: exact rescore (fp64 accum) of candidates, pick lexmin, gather.
// One warp per row.
// ---------------------------------------------------------------------------
__global__ __launch_bounds__(256) void vq2_kernel(
    const float* __restrict__ x,
    const float* __restrict__ embed,
    float* __restrict__ out)
{
    const int wid  = threadIdx.x >> 5;
    const int lane = threadIdx.x & 31;
    const int R = blockIdx.x * 8 + wid;

    int cnt = g_cnt[R];
    double bd = 1e300;
    int    bi = 0x7FFFFFFF;
    const float4* xr = (const float4*)(x + (size_t)R * D_DIM);

    if (cnt <= CAND_MAX) {
        for (int base = 0; base < cnt; base += 32) {
            int ci = base + lane;
            if (ci < cnt) {
                int cd = g_cand[R * CAND_MAX + ci];
                const float4* er = (const float4*)(embed + (size_t)cd * D_DIM);
                double dot = 0.0;
                #pragma unroll 4
                for (int q = 0; q < 64; q++) {
                    float4 a = xr[q], b = er[q];
                    dot += (double)a.x * b.x + (double)a.y * b.y
                         + (double)a.z * b.z + (double)a.w * b.w;
                }
                double s = (double)g_esq[cd] - 2.0 * dot;
                if (s < bd || (s == bd && cd < bi)) { bd = s; bi = cd; }
            }
        }
    } else {                                   // overflow fallback (near-never)
        for (int cd = lane; cd < N_TOT; cd += 32) {
            const float4* er = (const float4*)(embed + (size_t)cd * D_DIM);
            double dot = 0.0;
            for (int q = 0; q < 64; q++) {
                float4 a = xr[q], b = er[q];
                dot += (double)a.x * b.x + (double)a.y * b.y
                     + (double)a.z * b.z + (double)a.w * b.w;
            }
            double s = (double)g_esq[cd] - 2.0 * dot;
            if (s < bd || (s == bd && cd < bi)) { bd = s; bi = cd; }
        }
    }

    #pragma unroll
    for (int o = 16; o; o >>= 1) {
        double od = __shfl_xor_sync(0xFFFFFFFFu, bd, o);
        int    oi = __shfl_xor_sync(0xFFFFFFFFu, bi, o);
        if (od < bd || (od == bd && oi < bi)) { bd = od; bi = oi; }
    }

    if (lane == 0) out[(size_t)M_TOT * D_DIM + R] = (float)bi;

    const float4* src = (const float4*)(embed + (size_t)bi * D_DIM);
    float4* dst = (float4*)(out + (size_t)R * D_DIM);
    #pragma unroll
    for (int q = lane; q < 64; q += 32) dst[q] = src[q];
}

// ---------------------------------------------------------------------------
extern "C" void kernel_launch(void* const* d_in, const int* in_sizes, int n_in,
                              void* d_out, int out_size)
{
    const float* x     = (const float*)d_in[0];
    const float* embed = (const float*)d_in[1];
    float*       out   = (float*)d_out;

    init_kernel<<<(M_TOT + 255) / 256, 256>>>();
    norm_kernel<<<(2 * M_TOT * 32 + 255) / 256, 256>>>(x, embed);
    bpk_kernel<<<(N_TOT * D_DIM + 255) / 256, 256>>>(embed);

    cudaFuncSetAttribute(vq1_kernel,
                         cudaFuncAttributeMaxDynamicSharedMemorySize, SM_BYTES);
    vq1_kernel<<<M_TOT / TM, NTHREADS, SM_BYTES>>>(x);

    vq2_kernel<<<M_TOT / 8, 256>>>(x, embed, out);
}

// round 9
// speedup vs baseline: 2.7261x; 1.8464x over previous
#include <cuda_runtime.h>
#include <cstdint>
#include <math.h>

#define D_DIM    256
#define M_TOT    8192
#define N_TOT    8192
#define TM       64
#define TN       256
#define NTHREADS 512
#define KCH      32
#define TOTCH    ((N_TOT / TN) * (D_DIM / KCH))   // 256
#define CAND_MAX 256

#define SM_A_FLOATS (TM * D_DIM)          // 16384 floats = 64 KB
#define BUF_FLOATS  (TN * 40)             // row stride 40 floats -> 40960 B
#define SM_BYTES    (SM_A_FLOATS * 4 + 3 * BUF_FLOATS * 4)   // 188416

__device__ float    g_bpk[N_TOT * D_DIM];   // tf32-rounded, pair-permuted B
__device__ float    g_esq[N_TOT];
__device__ int      g_cand[M_TOT * CAND_MAX];
__device__ int      g_cnt[M_TOT];
__device__ unsigned g_mx2, g_me2;   // max sq norms; atomicMax-idempotent across replays

// ---------------------------------------------------------------------------
__device__ __forceinline__ float tf32_rn(float a) {
    uint32_t u;
    asm("cvt.rna.tf32.f32 %0, %1;" : "=r"(u) : "f"(a));
    return __uint_as_float(u);
}
__device__ __forceinline__ void mma1688(float* d, const uint32_t* a,
                                        const uint32_t* b) {
    asm volatile(
        "mma.sync.aligned.m16n8k8.row.col.f32.tf32.tf32.f32 "
        "{%0,%1,%2,%3}, {%4,%5,%6,%7}, {%8,%9}, {%0,%1,%2,%3};"
        : "+f"(d[0]), "+f"(d[1]), "+f"(d[2]), "+f"(d[3])
        : "r"(a[0]), "r"(a[1]), "r"(a[2]), "r"(a[3]), "r"(b[0]), "r"(b[1]));
}
__device__ __forceinline__ uint32_t smem_u32(const void* p) {
    uint32_t a;
    asm("{ .reg .u64 t; cvta.to.shared.u64 t, %1; cvt.u32.u64 %0, t; }"
        : "=r"(a) : "l"(p));
    return a;
}
__device__ __forceinline__ void cp16(uint32_t dst, const void* src) {
    asm volatile("cp.async.cg.shared.global [%0], [%1], 16;"
                 :: "r"(dst), "l"(src) : "memory");
}
#define CP_COMMIT() asm volatile("cp.async.commit_group;" ::: "memory")
#define CP_WAIT1()  asm volatile("cp.async.wait_group 1;" ::: "memory")
#define CP_WAIT0()  asm volatile("cp.async.wait_group 0;" ::: "memory")

__device__ __forceinline__ unsigned enc(float f) {
    unsigned u = __float_as_uint(f);
    return (u & 0x80000000u) ? ~u : (u | 0x80000000u);
}
__device__ __forceinline__ float dec(unsigned u) {
    return (u & 0x80000000u) ? __uint_as_float(u & 0x7FFFFFFFu)
                             : __uint_as_float(~u);
}

// ---------------------------------------------------------------------------
// prep_embed: warp per code row -> esq, bpk (tf32 permuted), block-max -> 1 atomic
// ---------------------------------------------------------------------------
__global__ __launch_bounds__(256) void prep_embed(const float* __restrict__ embed) {
    __shared__ float bmax[8];
    const int wid  = threadIdx.x >> 5;
    const int lane = threadIdx.x & 31;
    const int n = blockIdx.x * 8 + wid;

    const float* row = embed + (size_t)n * D_DIM;
    float s = 0.f;
    const float4* r4 = (const float4*)row;
    #pragma unroll
    for (int i = lane; i < 64; i += 32) {
        float4 v = r4[i];
        s += v.x * v.x + v.y * v.y + v.z * v.z + v.w * v.w;
    }
    #pragma unroll
    for (int o = 16; o; o >>= 1) s += __shfl_xor_sync(0xFFFFFFFFu, s, o);
    if (lane == 0) { g_esq[n] = s; bmax[wid] = s; }

    // pack: position p -> k = kc*32 + j*8 + kq + h*4  (p = kc*32+j*8+kq*2+h)
    #pragma unroll
    for (int t = 0; t < 2; t++) {
        int p0 = lane * 8 + t * 4;
        float4 w;
        float* wp = (float*)&w;
        #pragma unroll
        for (int e = 0; e < 4; e++) {
            int p = p0 + e;
            int kc = p >> 5, r = p & 31;
            int j = r >> 3, kq = (r >> 1) & 3, h = r & 1;
            wp[e] = tf32_rn(__ldg(row + kc * 32 + j * 8 + kq + h * 4));
        }
        ((float4*)(g_bpk + (size_t)n * D_DIM))[p0 >> 2] = w;
    }

    __syncthreads();
    if (threadIdx.x == 0) {
        float m = bmax[0];
        #pragma unroll
        for (int i = 1; i < 8; i++) m = fmaxf(m, bmax[i]);
        atomicMax(&g_me2, __float_as_uint(m));   // idempotent across replays
    }
}

// prep_x: warp per x row -> block-max ||x||^2 (1 atomic/block) + reset g_cnt
__global__ __launch_bounds__(256) void prep_x(const float* __restrict__ x) {
    __shared__ float bmax[8];
    const int wid  = threadIdx.x >> 5;
    const int lane = threadIdx.x & 31;
    const int r = blockIdx.x * 8 + wid;

    const float4* r4 = (const float4*)(x + (size_t)r * D_DIM);
    float s = 0.f;
    #pragma unroll
    for (int i = lane; i < 64; i += 32) {
        float4 v = r4[i];
        s += v.x * v.x + v.y * v.y + v.z * v.z + v.w * v.w;
    }
    #pragma unroll
    for (int o = 16; o; o >>= 1) s += __shfl_xor_sync(0xFFFFFFFFu, s, o);
    if (lane == 0) { bmax[wid] = s; g_cnt[r] = 0; }

    __syncthreads();
    if (threadIdx.x == 0) {
        float m = bmax[0];
        #pragma unroll
        for (int i = 1; i < 8; i++) m = fmaxf(m, bmax[i]);
        atomicMax(&g_mx2, __float_as_uint(m));
    }
}

// ---------------------------------------------------------------------------
// Pass 1: 1xTF32 GEMM + running-min + candidate append.
// 512 thr / 16 warps (2m x 8n); warp tile 32x32; K-chunks 32, cp.async 3-buf.
// ---------------------------------------------------------------------------
extern __shared__ float dsm[];

__device__ __forceinline__ void append_cand(int grow, int col) {
    int idx = atomicAdd(&g_cnt[grow], 1);
    if (idx < CAND_MAX) g_cand[grow * CAND_MAX + idx] = col;
}

__global__ __launch_bounds__(NTHREADS, 1) void vq1_kernel(
    const float* __restrict__ x)
{
    __shared__ unsigned red[TM];
    float* smA = dsm;
    const uint32_t smBase = smem_u32(dsm);

    const int tid  = threadIdx.x;
    const int lane = tid & 31;
    const int wid  = tid >> 5;
    const int wm   = wid & 1;          // m half (32 rows)
    const int wn   = wid >> 1;         // n eighth (32 cols)
    const int mBase = blockIdx.x * TM;

    if (tid < TM) red[tid] = 0xFFFFFFFFu;

    const float th = 4.2e-3f * sqrtf(__uint_as_float(g_mx2) *
                                     __uint_as_float(g_me2)) + 0.02f;

    // prologue: B chunks 0,1 (n-tile 0)
    #pragma unroll
    for (int c0 = 0; c0 < 2; c0++) {
        uint32_t dstB = smBase + SM_A_FLOATS * 4 + (uint32_t)c0 * (BUF_FLOATS * 4);
        const float* src = g_bpk + c0 * KCH;
        #pragma unroll
        for (int i = 0; i < 4; i++) {
            int g = tid + i * NTHREADS, row = g >> 3, seg = g & 7;
            cp16(dstB + row * 160 + seg * 16, src + row * 256 + seg * 4);
        }
        CP_COMMIT();
    }

    // A: 64 rows x 256 k, tf32-rounded, mma-fragment-permuted
    #pragma unroll 4
    for (int s = 0; s < 8; s++) {
        int fidx = tid + s * NTHREADS;
        int row = fidx >> 6, q = fidx & 63;
        float4 v = ((const float4*)(x + (size_t)(mBase + row) * D_DIM))[q];
        int mt = row >> 4, ml = row & 15;
        float vv[4] = {v.x, v.y, v.z, v.w};
        #pragma unroll
        for (int e = 0; e < 4; e++) {
            int kk = q * 4 + e;
            int k8 = kk >> 3, c = kk & 7;
            int t    = ((ml & 7) << 2) | (c & 3);
            int slot = ((ml >> 3) & 1) | (((c >> 2) & 1) << 1);
            smA[(mt * 32 + k8) * 128 + t * 4 + slot] = tf32_rn(vv[e]);
        }
    }

    float acc[2][4][4];

    for (int c = 0; c < TOTCH; c++) {
        if (c + 1 < TOTCH) CP_WAIT1(); else CP_WAIT0();
        __syncthreads();

        const int kc  = c & 7;
        const int ntB = (c >> 3) * TN;

        if (kc == 0) {
            #pragma unroll
            for (int i = 0; i < 2; i++)
                #pragma unroll
                for (int j = 0; j < 4; j++)
                    #pragma unroll
                    for (int e = 0; e < 4; e++) acc[i][j][e] = 0.f;
        }

        const float* bb = dsm + SM_A_FLOATS + (c % 3) * BUF_FLOATS;

        #pragma unroll
        for (int j = 0; j < 4; j++) {
            const int k8g = kc * 4 + j;
            uint32_t aF[2][4];
            #pragma unroll
            for (int mt = 0; mt < 2; mt++) {
                int mtg = wm * 2 + mt;
                float4 af = *(const float4*)&smA[(mtg * 32 + k8g) * 128 + lane * 4];
                aF[mt][0] = __float_as_uint(af.x);
                aF[mt][1] = __float_as_uint(af.y);
                aF[mt][2] = __float_as_uint(af.z);
                aF[mt][3] = __float_as_uint(af.w);
            }
            #pragma unroll
            for (int ntl = 0; ntl < 4; ntl++) {
                int nloc = wn * 32 + ntl * 8 + (lane >> 2);
                float2 bp = *(const float2*)&bb[nloc * 40 + (j * 4 + (lane & 3)) * 2];
                uint32_t bF[2] = {__float_as_uint(bp.x), __float_as_uint(bp.y)};
                mma1688(acc[0][ntl], aF[0], bF);
                mma1688(acc[1][ntl], aF[1], bF);
            }
        }

        if (c + 2 < TOTCH) {
            int nc = c + 2;
            uint32_t dstB = smBase + SM_A_FLOATS * 4
                          + (uint32_t)(nc % 3) * (BUF_FLOATS * 4);
            const float* src = g_bpk + (size_t)((nc >> 3) * TN) * 256
                             + (nc & 7) * KCH;
            #pragma unroll
            for (int i = 0; i < 4; i++) {
                int g = tid + i * NTHREADS, row = g >> 3, seg = g & 7;
                cp16(dstB + row * 160 + seg * 16, src + row * 256 + seg * 4);
            }
            CP_COMMIT();
        }

        if (kc == 7) {
            float rmin[4] = {3.4e38f, 3.4e38f, 3.4e38f, 3.4e38f};
            #pragma unroll
            for (int mt = 0; mt < 2; mt++)
                #pragma unroll
                for (int ntl = 0; ntl < 4; ntl++) {
                    int c0 = ntB + wn * 32 + ntl * 8 + 2 * (lane & 3);
                    float e0 = __ldg(&g_esq[c0]);
                    float e1 = __ldg(&g_esq[c0 + 1]);
                    float s0 = e0 - 2.0f * acc[mt][ntl][0];
                    float s1 = e1 - 2.0f * acc[mt][ntl][1];
                    float s2 = e0 - 2.0f * acc[mt][ntl][2];
                    float s3 = e1 - 2.0f * acc[mt][ntl][3];
                    rmin[mt*2]   = fminf(rmin[mt*2],   fminf(s0, s1));
                    rmin[mt*2+1] = fminf(rmin[mt*2+1], fminf(s2, s3));
                }
            #pragma unroll
            for (int q = 0; q < 4; q++) {
                int r = (wm * 2 + (q >> 1)) * 16 + (lane >> 2) + (q & 1) * 8;
                atomicMin(&red[r], enc(rmin[q]));
            }
            __syncthreads();
            #pragma unroll
            for (int mt = 0; mt < 2; mt++) {
                int r0 = (wm * 2 + mt) * 16 + (lane >> 2);
                float t0 = dec(red[r0]) + th;
                float t1 = dec(red[r0 + 8]) + th;
                #pragma unroll
                for (int ntl = 0; ntl < 4; ntl++) {
                    int c0 = ntB + wn * 32 + ntl * 8 + 2 * (lane & 3);
                    float e0 = __ldg(&g_esq[c0]);
                    float e1 = __ldg(&g_esq[c0 + 1]);
                    float s0 = e0 - 2.0f * acc[mt][ntl][0];
                    float s1 = e1 - 2.0f * acc[mt][ntl][1];
                    float s2 = e0 - 2.0f * acc[mt][ntl][2];
                    float s3 = e1 - 2.0f * acc[mt][ntl][3];
                    if (s0 <= t0) append_cand(mBase + r0, c0);
                    if (s1 <= t0) append_cand(mBase + r0, c0 + 1);
                    if (s2 <= t1) append_cand(mBase + r0 + 8, c0);
                    if (s3 <= t1) append_cand(mBase + r0 + 8, c0 + 1);
                }
            }
        }
    }
}

// ---------------------------------------------------------------------------
// Pass 2: exact rescore, warp per row, WHOLE WARP per candidate
// (lane owns 8 dims: 8-term fp64 chain + shfl reduce — no long serial chain).
// ---------------------------------------------------------------------------
__global__ __launch_bounds__(256) void vq2_kernel(
    const float* __restrict__ x,
    const float* __restrict__ embed,
    float* __restrict__ out)
{
    const int wid  = threadIdx.x >> 5;
    const int lane = threadIdx.x & 31;
    const int R = blockIdx.x * 8 + wid;

    // lane's 8 x-dims
    const float4* xr = (const float4*)(x + (size_t)R * D_DIM);
    float4 xa = xr[lane * 2], xb = xr[lane * 2 + 1];

    int cnt = g_cnt[R];
    double bd = 1e300;
    int    bi = 0x7FFFFFFF;

    auto score_one = [&](int cd) {
        const float4* er = (const float4*)(embed + (size_t)cd * D_DIM);
        float4 ea = er[lane * 2], eb = er[lane * 2 + 1];
        double dot = (double)xa.x * ea.x + (double)xa.y * ea.y
                   + (double)xa.z * ea.z + (double)xa.w * ea.w
                   + (double)xb.x * eb.x + (double)xb.y * eb.y
                   + (double)xb.z * eb.z + (double)xb.w * eb.w;
        #pragma unroll
        for (int o = 16; o; o >>= 1)
            dot += __shfl_xor_sync(0xFFFFFFFFu, dot, o);
        double s = (double)g_esq[cd] - 2.0 * dot;     // identical on all lanes
        if (s < bd || (s == bd && cd < bi)) { bd = s; bi = cd; }
    };

    if (cnt <= CAND_MAX) {
        for (int ci = 0; ci < cnt; ci++)
            score_one(g_cand[R * CAND_MAX + ci]);
    } else {                                           // near-never fallback
        for (int cd = 0; cd < N_TOT; cd++) score_one(cd);
    }

    if (lane == 0) out[(size_t)M_TOT * D_DIM + R] = (float)bi;

    const float4* src = (const float4*)(embed + (size_t)bi * D_DIM);
    float4* dst = (float4*)(out + (size_t)R * D_DIM);
    #pragma unroll
    for (int q = lane; q < 64; q += 32) dst[q] = src[q];
}

// ---------------------------------------------------------------------------
extern "C" void kernel_launch(void* const* d_in, const int* in_sizes, int n_in,
                              void* d_out, int out_size)
{
    const float* x     = (const float*)d_in[0];
    const float* embed = (const float*)d_in[1];
    float*       out   = (float*)d_out;

    prep_embed<<<N_TOT / 8, 256>>>(embed);
    prep_x<<<M_TOT / 8, 256>>>(x);

    cudaFuncSetAttribute(vq1_kernel,
                         cudaFuncAttributeMaxDynamicSharedMemorySize, SM_BYTES);
    vq1_kernel<<<M_TOT / TM, NTHREADS, SM_BYTES>>>(x);

    vq2_kernel<<<M_TOT / 8, 256>>>(x, embed, out);
}